// round 9
// baseline (speedup 1.0000x reference)
#include <cuda_runtime.h>

// Problem constants
#define BSZ   4096
#define PSZ   32
#define EMB   128
#define HDIM  768
#define MROWS 16            // batch rows per MLP block
#define NBUCKET (BSZ / MROWS)   // 256
#define ARRIVALS 48         // 16 rows x 3 groups per bucket

// Scratch: intermediate H [B, 768] (12.6 MB)
__device__ float g_H[BSZ * HDIM];
// Producer->consumer bucket counters
__device__ unsigned int g_cnt[NBUCKET];

__global__ void zero_cnt_kernel() { g_cnt[threadIdx.x] = 0u; }

__device__ __forceinline__ float4 relu_step(float4 x, float4 w, float4 y, float4 bm) {
    float4 r;
    r.x = fmaxf(fmaf(x.x * w.x, y.x, bm.x), 0.f);
    r.y = fmaxf(fmaf(x.y * w.y, y.y, bm.y), 0.f);
    r.z = fmaxf(fmaf(x.z * w.z, y.z, bm.z), 0.f);
    r.w = fmaxf(fmaf(x.w * w.w, y.w, bm.w), 0.f);
    return r;
}

struct PathSmem {
    float sW[3 * EMB];
    float sB[3 * EMB];
    float sAcc[8][256];
    float sCnt[8];
};

// One block per (batch row b, group). 8 warps; warp w handles paths
// p = w, w+8, w+16, w+24 with 1-path lookahead prefetch of embedding rows.
template<int L>
__device__ __forceinline__ void path_body(
    PathSmem& sm,
    const int*   __restrict__ ents,
    const int*   __restrict__ mids,
    const float* __restrict__ counts,
    const float* __restrict__ E,
    const float* __restrict__ Wm,
    const float* __restrict__ Bm,
    int gofs)
{
    const int b    = blockIdx.x;
    const int tid  = threadIdx.x;
    const int wid  = tid >> 5;
    const int lane = tid & 31;

    for (int i = tid; i < 3 * EMB; i += 256) { sm.sW[i] = Wm[i]; sm.sB[i] = Bm[i]; }
    __syncthreads();

    int   e[4][L + 1];
    int   m[4][L];
    float cnt[4];
    #pragma unroll
    for (int pp = 0; pp < 4; pp++) {
        const long base = (long)b * PSZ + (wid + pp * 8);
        const int* ep = ents + base * (L + 1);
        const int* mp = mids + base * L;
        #pragma unroll
        for (int i = 0; i <= L; i++) e[pp][i] = ep[i];
        #pragma unroll
        for (int i = 0; i < L; i++)  m[pp][i] = mp[i];
        cnt[pp] = counts[base];
    }

    float4 a1 = make_float4(0.f, 0.f, 0.f, 0.f);
    float4 a2 = make_float4(0.f, 0.f, 0.f, 0.f);
    float  cs = 0.f;

    float4 buf[2][L + 1];
    #pragma unroll
    for (int i = 0; i <= L; i++)
        buf[0][i] = *(const float4*)(E + (long)e[0][i] * EMB + lane * 4);

    #pragma unroll
    for (int pp = 0; pp < 4; pp++) {
        if (pp < 3) {
            #pragma unroll
            for (int i = 0; i <= L; i++)
                buf[(pp + 1) & 1][i] =
                    *(const float4*)(E + (long)e[pp + 1][i] * EMB + lane * 4);
        }
        float4 (&rows)[L + 1] = buf[pp & 1];

        // forward
        float4 x = rows[0];
        #pragma unroll
        for (int i = 0; i < L; i++) {
            float4 w  = *(const float4*)(sm.sW + m[pp][i] * EMB + lane * 4);
            float4 bb = *(const float4*)(sm.sB + m[pp][i] * EMB + lane * 4);
            x = relu_step(x, w, rows[i + 1], bb);
        }
        const float4 o1 = x;

        // backward: start x and (stale) y are both E[ents[L]]
        const float4 yl = rows[L];
        x = yl;
        #pragma unroll
        for (int i = L - 1; i >= 0; i--) {
            float4 w  = *(const float4*)(sm.sW + m[pp][i] * EMB + lane * 4);
            float4 bb = *(const float4*)(sm.sB + m[pp][i] * EMB + lane * 4);
            x = relu_step(x, w, yl, bb);
        }

        const float c0 = cnt[pp];
        a1.x += c0 * o1.x; a1.y += c0 * o1.y; a1.z += c0 * o1.z; a1.w += c0 * o1.w;
        a2.x += c0 * x.x;  a2.y += c0 * x.y;  a2.z += c0 * x.z;  a2.w += c0 * x.w;
        cs   += c0;
    }

    ((float4*)sm.sAcc[wid])[lane]         = a1;
    ((float4*)(sm.sAcc[wid] + 128))[lane] = a2;
    if (lane == 0) sm.sCnt[wid] = cs;
    __syncthreads();

    float s = 0.f, csum = 0.f;
    #pragma unroll
    for (int w = 0; w < 8; w++) { s += sm.sAcc[w][tid]; csum += sm.sCnt[w]; }
    g_H[(long)b * HDIM + gofs + tid] = s / csum;

    // Signal bucket completion (release): all 256 H-writes of this block done.
    __syncthreads();
    if (tid == 0) {
        __threadfence();
        atomicAdd(&g_cnt[b >> 4], 1u);
    }
}

__global__ __launch_bounds__(256) void paths_kernel(
    const int* __restrict__ ent1, const int* __restrict__ mid1, const float* __restrict__ c1,
    const int* __restrict__ ent2, const int* __restrict__ mid2, const float* __restrict__ c2,
    const int* __restrict__ ent3, const int* __restrict__ mid3, const float* __restrict__ c3,
    const float* __restrict__ E, const float* __restrict__ Wm, const float* __restrict__ Bm)
{
    __shared__ PathSmem sm;
    const int g = blockIdx.y;
    if (g == 0)      path_body<1>(sm, ent1, mid1, c1, E, Wm, Bm, 0);
    else if (g == 1) path_body<2>(sm, ent2, mid2, c2, E, Wm, Bm, 256);
    else             path_body<3>(sm, ent3, mid3, c3, E, Wm, Bm, 512);
}

// ────────────────────────────────────────────────────────────────────────
// MLP head (R4 plain-fp32 version — best by end-to-end timing):
// 16 rows/block, 512 threads, 256 blocks. Spin-waits on its bucket counter
// so it can be launched concurrently with paths_kernel.
// ────────────────────────────────────────────────────────────────────────
__global__ __launch_bounds__(512) void mlp_kernel(
    const float* __restrict__ W1, const float* __restrict__ b1,
    const float* __restrict__ W2, const float* __restrict__ b2,
    const float* __restrict__ W3, const float* __restrict__ b3,
    float* __restrict__ out)
{
    __shared__ float smem[MROWS * HDIM];        // 48 KB
    float* const sH = smem;

    const int b0  = blockIdx.x * MROWS;
    const int tid = threadIdx.x;

    // Wait for all 48 producer blocks of this bucket (acquire).
    if (tid == 0) {
        unsigned int v;
        const unsigned int* addr = &g_cnt[blockIdx.x];
        do {
            asm volatile("ld.acquire.gpu.global.u32 %0, [%1];"
                         : "=r"(v) : "l"(addr));
            if (v < ARRIVALS) __nanosleep(128);
        } while (v < ARRIVALS);
    }
    __syncthreads();

    // Load full H tile (3072 float4, 6 per thread)
    {
        const float4* src = (const float4*)(g_H + (long)b0 * HDIM);
        float4*       dst = (float4*)sH;
        #pragma unroll
        for (int i = 0; i < (MROWS * HDIM / 4) / 512; i++)
            dst[tid + i * 512] = src[tid + i * 512];
    }
    __syncthreads();

    // ── Phase A: h1 = relu(H @ W1 + b1), [16,128] ────────────────────────
    const int c     = tid & 127;
    const int rbase = (tid >> 7) * 4;     // 0,4,8,12
    float acc[4];
    {
        const float bias1 = b1[c];
        #pragma unroll
        for (int r = 0; r < 4; r++) acc[r] = bias1;
    }

    #pragma unroll 4
    for (int kb = 0; kb < HDIM; kb += 4) {
        const float* wp = W1 + kb * 128 + c;
        const float w0 = __ldg(wp);
        const float w1 = __ldg(wp + 128);
        const float w2 = __ldg(wp + 256);
        const float w3 = __ldg(wp + 384);
        #pragma unroll
        for (int r = 0; r < 4; r++) {
            const float4 h = *(const float4*)(sH + (rbase + r) * HDIM + kb);
            float a = acc[r];
            a = fmaf(h.x, w0, a);
            a = fmaf(h.y, w1, a);
            a = fmaf(h.z, w2, a);
            a = fmaf(h.w, w3, a);
            acc[r] = a;
        }
    }
    __syncthreads();          // everyone done reading sH

    float* const sh1 = smem;                 // [16][128]
    float* const sh2 = smem + MROWS * 128;   // [16][32]
    #pragma unroll
    for (int r = 0; r < 4; r++)
        sh1[(rbase + r) * 128 + c] = fmaxf(acc[r], 0.f);
    __syncthreads();

    // ── Phase B: h2 = relu(h1 @ W2 + b2), [16,32] — 512 thr = 16r × 32c ──
    {
        const int c2 = tid & 31;
        const int r  = tid >> 5;   // 0..15
        float a = b2[c2];
        #pragma unroll 8
        for (int k = 0; k < 128; k += 4) {
            const float4 h = *(const float4*)(sh1 + r * 128 + k);
            a = fmaf(h.x, __ldg(W2 + (k    ) * 32 + c2), a);
            a = fmaf(h.y, __ldg(W2 + (k + 1) * 32 + c2), a);
            a = fmaf(h.z, __ldg(W2 + (k + 2) * 32 + c2), a);
            a = fmaf(h.w, __ldg(W2 + (k + 3) * 32 + c2), a);
        }
        sh2[r * 32 + c2] = fmaxf(a, 0.f);
    }
    __syncthreads();

    // ── Phase C: out = h2 @ W3 + b3, [16,1] ─────────────────────────────
    if (tid < MROWS) {
        float a = b3[0];
        #pragma unroll
        for (int k = 0; k < 32; k++) a = fmaf(sh2[tid * 32 + k], W3[k], a);
        out[b0 + tid] = a;
    }
}

extern "C" void kernel_launch(void* const* d_in, const int* in_sizes, int n_in,
                              void* d_out, int out_size)
{
    // Side stream + events: created ONCE on the first (correctness) call,
    // before graph capture. Afterwards only capturable ops are issued.
    static cudaStream_t s2  = nullptr;
    static cudaEvent_t  evZ = nullptr, evJ = nullptr;
    if (s2 == nullptr) {
        cudaStreamCreateWithFlags(&s2, cudaStreamNonBlocking);
        cudaEventCreateWithFlags(&evZ, cudaEventDisableTiming);
        cudaEventCreateWithFlags(&evJ, cudaEventDisableTiming);
    }

    const bool dictOrder = (in_sizes[2] == BSZ * PSZ);

    const int *ent1, *mid1, *ent2, *mid2, *ent3, *mid3;
    const float *c1, *c2, *c3;
    if (dictOrder) {
        ent1 = (const int*)d_in[0]; mid1 = (const int*)d_in[1]; c1 = (const float*)d_in[2];
        ent2 = (const int*)d_in[3]; mid2 = (const int*)d_in[4]; c2 = (const float*)d_in[5];
        ent3 = (const int*)d_in[6]; mid3 = (const int*)d_in[7]; c3 = (const float*)d_in[8];
    } else {
        ent1 = (const int*)d_in[0]; mid1 = (const int*)d_in[1];
        ent2 = (const int*)d_in[2]; mid2 = (const int*)d_in[3];
        ent3 = (const int*)d_in[4]; mid3 = (const int*)d_in[5];
        c1 = (const float*)d_in[6]; c2 = (const float*)d_in[7]; c3 = (const float*)d_in[8];
    }
    const float* E  = (const float*)d_in[9];
    const float* Wm = (const float*)d_in[10];
    const float* Bm = (const float*)d_in[11];
    const float* W1 = (const float*)d_in[12];
    const float* b1 = (const float*)d_in[13];
    const float* W2 = (const float*)d_in[14];
    const float* b2 = (const float*)d_in[15];
    const float* W3 = (const float*)d_in[16];
    const float* b3 = (const float*)d_in[17];

    const cudaStream_t s0 = (cudaStream_t)0;

    // Reset bucket counters, then fan out to both streams.
    zero_cnt_kernel<<<1, NBUCKET, 0, s0>>>();
    cudaEventRecord(evZ, s0);
    cudaStreamWaitEvent(s2, evZ, 0);

    // Producer: all paths blocks (stream 0).
    dim3 pgrid(BSZ, 3);
    paths_kernel<<<pgrid, 256, 0, s0>>>(ent1, mid1, c1, ent2, mid2, c2,
                                        ent3, mid3, c3, E, Wm, Bm);

    // Consumer: full-grid mlp, concurrent, self-synchronizing per bucket.
    mlp_kernel<<<BSZ / MROWS, 512, 0, s2>>>(W1, b1, W2, b2, W3, b3, (float*)d_out);

    // Join side stream back into stream 0.
    cudaEventRecord(evJ, s2);
    cudaStreamWaitEvent(s0, evJ, 0);
}

// round 10
// speedup vs baseline: 1.2387x; 1.2387x over previous
#include <cuda_runtime.h>

// Problem constants
#define BSZ   4096
#define PSZ   32
#define EMB   128
#define HDIM  768
#define MROWS 16            // batch rows per MLP block

// Scratch: intermediate H [B, 768] (12.6 MB)
__device__ float g_H[BSZ * HDIM];

// ── cp.async helpers ────────────────────────────────────────────────────
__device__ __forceinline__ unsigned int smem_u32(const void* p) {
    return (unsigned int)__cvta_generic_to_shared(p);
}
__device__ __forceinline__ void cp_async16(unsigned int saddr, const void* gptr) {
    asm volatile("cp.async.cg.shared.global [%0], [%1], 16;" :: "r"(saddr), "l"(gptr));
}
__device__ __forceinline__ void cp_commit() {
    asm volatile("cp.async.commit_group;");
}
template<int N> __device__ __forceinline__ void cp_wait() {
    asm volatile("cp.async.wait_group %0;" :: "n"(N));
}

__device__ __forceinline__ float4 relu_step(float4 x, float4 w, float4 y, float4 bm) {
    float4 r;
    r.x = fmaxf(fmaf(x.x * w.x, y.x, bm.x), 0.f);
    r.y = fmaxf(fmaf(x.y * w.y, y.y, bm.y), 0.f);
    r.z = fmaxf(fmaf(x.z * w.z, y.z, bm.z), 0.f);
    r.w = fmaxf(fmaf(x.w * w.w, y.w, bm.w), 0.f);
    return r;
}

// smem rows region: per warp 2 slots × 4 rows × 128 floats
#define SLOT_F  512          // floats per slot (4 rows)
#define WARP_F  1024         // floats per warp (2 slots)

struct PathSmem {
    float sW[3 * EMB];        // 1.5 KB
    float sB[3 * EMB];        // 1.5 KB
    float sAcc[8][256];       // 8 KB
    float sCnt[8];
    float rows[8 * WARP_F];   // 32 KB — cp.async landing buffers
};

// One block per (batch row b, group). 8 warps; warp w handles paths
// p = w, w+8, w+16, w+24 via a 2-deep cp.async smem pipeline.
template<int L>
__device__ __forceinline__ void path_body(
    PathSmem& sm,
    const int*   __restrict__ ents,    // [B,P,L+1]
    const int*   __restrict__ mids,    // [B,P,L]
    const float* __restrict__ counts,  // [B,P]
    const float* __restrict__ E,       // [100000,128]
    const float* __restrict__ Wm,
    const float* __restrict__ Bm,
    int gofs)
{
    const int b    = blockIdx.x;
    const int tid  = threadIdx.x;
    const int wid  = tid >> 5;
    const int lane = tid & 31;

    for (int i = tid; i < 3 * EMB; i += 256) { sm.sW[i] = Wm[i]; sm.sB[i] = Bm[i]; }

    // Hoist indices + counts for this warp's 4 paths (warp-uniform loads)
    int   e[4][L + 1];
    int   m[4][L];
    float cnt[4];
    #pragma unroll
    for (int pp = 0; pp < 4; pp++) {
        const long base = (long)b * PSZ + (wid + pp * 8);
        const int* ep = ents + base * (L + 1);
        const int* mp = mids + base * L;
        #pragma unroll
        for (int i = 0; i <= L; i++) e[pp][i] = ep[i];
        #pragma unroll
        for (int i = 0; i < L; i++)  m[pp][i] = mp[i];
        cnt[pp] = counts[base];
    }
    __syncthreads();   // sW/sB ready (placed after index loads to overlap)

    float* const myrows = sm.rows + wid * WARP_F;
    const unsigned int myrows_s = smem_u32(myrows) + lane * 16;

    // Issue all rows of path pp into slot s (one 16B cp.async per lane per row)
    auto issue = [&](int pp, int s) {
        #pragma unroll
        for (int i = 0; i <= L; i++)
            cp_async16(myrows_s + (s * SLOT_F + i * EMB) * 4,
                       E + (long)e[pp][i] * EMB + lane * 4);
        cp_commit();
    };

    float4 a1 = make_float4(0.f, 0.f, 0.f, 0.f);
    float4 a2 = make_float4(0.f, 0.f, 0.f, 0.f);
    float  cs = 0.f;

    // Consume path pp from slot s
    auto process = [&](int pp, int s) {
        const float* rb = myrows + s * SLOT_F + lane * 4;
        // forward
        float4 x = *(const float4*)(rb);
        #pragma unroll
        for (int i = 0; i < L; i++) {
            const float4 y  = *(const float4*)(rb + (i + 1) * EMB);
            const float4 w  = *(const float4*)(sm.sW + m[pp][i] * EMB + lane * 4);
            const float4 bb = *(const float4*)(sm.sB + m[pp][i] * EMB + lane * 4);
            x = relu_step(x, w, y, bb);
        }
        const float4 o1 = x;
        // backward: start x and (stale) y are both E[ents[L]]
        const float4 yl = *(const float4*)(rb + L * EMB);
        x = yl;
        #pragma unroll
        for (int i = L - 1; i >= 0; i--) {
            const float4 w  = *(const float4*)(sm.sW + m[pp][i] * EMB + lane * 4);
            const float4 bb = *(const float4*)(sm.sB + m[pp][i] * EMB + lane * 4);
            x = relu_step(x, w, yl, bb);
        }
        const float c0 = cnt[pp];
        a1.x += c0 * o1.x; a1.y += c0 * o1.y; a1.z += c0 * o1.z; a1.w += c0 * o1.w;
        a2.x += c0 * x.x;  a2.y += c0 * x.y;  a2.z += c0 * x.z;  a2.w += c0 * x.w;
        cs   += c0;
    };

    // 2-deep software pipeline over 4 paths
    issue(0, 0);
    issue(1, 1);
    cp_wait<1>(); process(0, 0); issue(2, 0);
    cp_wait<1>(); process(1, 1); issue(3, 1);
    cp_wait<1>(); process(2, 0);
    cp_wait<0>(); process(3, 1);

    ((float4*)sm.sAcc[wid])[lane]         = a1;   // dims 0..127
    ((float4*)(sm.sAcc[wid] + 128))[lane] = a2;   // dims 128..255
    if (lane == 0) sm.sCnt[wid] = cs;
    __syncthreads();

    // Deterministic reduce across the 8 warps
    float s = 0.f, csum = 0.f;
    #pragma unroll
    for (int w = 0; w < 8; w++) { s += sm.sAcc[w][tid]; csum += sm.sCnt[w]; }
    g_H[(long)b * HDIM + gofs + tid] = s / csum;
}

__global__ __launch_bounds__(256) void paths_kernel(
    const int* __restrict__ ent1, const int* __restrict__ mid1, const float* __restrict__ c1,
    const int* __restrict__ ent2, const int* __restrict__ mid2, const float* __restrict__ c2,
    const int* __restrict__ ent3, const int* __restrict__ mid3, const float* __restrict__ c3,
    const float* __restrict__ E, const float* __restrict__ Wm, const float* __restrict__ Bm)
{
    __shared__ PathSmem sm;
    const int g = blockIdx.y;
    if (g == 0)      path_body<1>(sm, ent1, mid1, c1, E, Wm, Bm, 0);
    else if (g == 1) path_body<2>(sm, ent2, mid2, c2, E, Wm, Bm, 256);
    else             path_body<3>(sm, ent3, mid3, c3, E, Wm, Bm, 512);
}

// ────────────────────────────────────────────────────────────────────────
// MLP head (R4 plain-fp32 — best by end-to-end timing):
// 16 rows/block, 512 threads, 256 blocks.
// ────────────────────────────────────────────────────────────────────────
__global__ __launch_bounds__(512) void mlp_kernel(
    const float* __restrict__ W1, const float* __restrict__ b1,
    const float* __restrict__ W2, const float* __restrict__ b2,
    const float* __restrict__ W3, const float* __restrict__ b3,
    float* __restrict__ out)
{
    __shared__ float smem[MROWS * HDIM];        // 48 KB
    float* const sH = smem;

    const int b0  = blockIdx.x * MROWS;
    const int tid = threadIdx.x;

    // Load full H tile (3072 float4, 6 per thread)
    {
        const float4* src = (const float4*)(g_H + (long)b0 * HDIM);
        float4*       dst = (float4*)sH;
        #pragma unroll
        for (int i = 0; i < (MROWS * HDIM / 4) / 512; i++)
            dst[tid + i * 512] = src[tid + i * 512];
    }
    __syncthreads();

    // ── Phase A: h1 = relu(H @ W1 + b1), [16,128] ────────────────────────
    const int c     = tid & 127;
    const int rbase = (tid >> 7) * 4;     // 0,4,8,12
    float acc[4];
    {
        const float bias1 = b1[c];
        #pragma unroll
        for (int r = 0; r < 4; r++) acc[r] = bias1;
    }

    #pragma unroll 4
    for (int kb = 0; kb < HDIM; kb += 4) {
        const float* wp = W1 + kb * 128 + c;
        const float w0 = __ldg(wp);
        const float w1 = __ldg(wp + 128);
        const float w2 = __ldg(wp + 256);
        const float w3 = __ldg(wp + 384);
        #pragma unroll
        for (int r = 0; r < 4; r++) {
            const float4 h = *(const float4*)(sH + (rbase + r) * HDIM + kb);
            float a = acc[r];
            a = fmaf(h.x, w0, a);
            a = fmaf(h.y, w1, a);
            a = fmaf(h.z, w2, a);
            a = fmaf(h.w, w3, a);
            acc[r] = a;
        }
    }
    __syncthreads();          // everyone done reading sH

    float* const sh1 = smem;                 // [16][128]
    float* const sh2 = smem + MROWS * 128;   // [16][32]
    #pragma unroll
    for (int r = 0; r < 4; r++)
        sh1[(rbase + r) * 128 + c] = fmaxf(acc[r], 0.f);
    __syncthreads();

    // ── Phase B: h2 = relu(h1 @ W2 + b2), [16,32] — 512 thr = 16r × 32c ──
    {
        const int c2 = tid & 31;
        const int r  = tid >> 5;   // 0..15
        float a = b2[c2];
        #pragma unroll 8
        for (int k = 0; k < 128; k += 4) {
            const float4 h = *(const float4*)(sh1 + r * 128 + k);
            a = fmaf(h.x, __ldg(W2 + (k    ) * 32 + c2), a);
            a = fmaf(h.y, __ldg(W2 + (k + 1) * 32 + c2), a);
            a = fmaf(h.z, __ldg(W2 + (k + 2) * 32 + c2), a);
            a = fmaf(h.w, __ldg(W2 + (k + 3) * 32 + c2), a);
        }
        sh2[r * 32 + c2] = fmaxf(a, 0.f);
    }
    __syncthreads();

    // ── Phase C: out = h2 @ W3 + b3, [16,1] ─────────────────────────────
    if (tid < MROWS) {
        float a = b3[0];
        #pragma unroll
        for (int k = 0; k < 32; k++) a = fmaf(sh2[tid * 32 + k], W3[k], a);
        out[b0 + tid] = a;
    }
}

extern "C" void kernel_launch(void* const* d_in, const int* in_sizes, int n_in,
                              void* d_out, int out_size)
{
    const bool dictOrder = (in_sizes[2] == BSZ * PSZ);

    const int *ent1, *mid1, *ent2, *mid2, *ent3, *mid3;
    const float *c1, *c2, *c3;
    if (dictOrder) {
        ent1 = (const int*)d_in[0]; mid1 = (const int*)d_in[1]; c1 = (const float*)d_in[2];
        ent2 = (const int*)d_in[3]; mid2 = (const int*)d_in[4]; c2 = (const float*)d_in[5];
        ent3 = (const int*)d_in[6]; mid3 = (const int*)d_in[7]; c3 = (const float*)d_in[8];
    } else {
        ent1 = (const int*)d_in[0]; mid1 = (const int*)d_in[1];
        ent2 = (const int*)d_in[2]; mid2 = (const int*)d_in[3];
        ent3 = (const int*)d_in[4]; mid3 = (const int*)d_in[5];
        c1 = (const float*)d_in[6]; c2 = (const float*)d_in[7]; c3 = (const float*)d_in[8];
    }
    const float* E  = (const float*)d_in[9];
    const float* Wm = (const float*)d_in[10];
    const float* Bm = (const float*)d_in[11];
    const float* W1 = (const float*)d_in[12];
    const float* b1 = (const float*)d_in[13];
    const float* W2 = (const float*)d_in[14];
    const float* b2 = (const float*)d_in[15];
    const float* W3 = (const float*)d_in[16];
    const float* b3 = (const float*)d_in[17];

    dim3 pgrid(BSZ, 3);
    paths_kernel<<<pgrid, 256>>>(ent1, mid1, c1, ent2, mid2, c2, ent3, mid3, c3,
                                 E, Wm, Bm);
    mlp_kernel<<<BSZ / MROWS, 512>>>(W1, b1, W2, b2, W3, b3, (float*)d_out);
}

// round 11
// speedup vs baseline: 1.4936x; 1.2057x over previous
#include <cuda_runtime.h>

// Problem constants
#define BSZ   4096
#define PSZ   32
#define EMB   128
#define HDIM  768
#define MROWS 16            // batch rows per MLP block

// Scratch: intermediate H [B, 768] (12.6 MB)
__device__ float g_H[BSZ * HDIM];

__device__ __forceinline__ float4 relu_step(float4 x, float4 w, float4 y, float4 bm) {
    float4 r;
    r.x = fmaxf(fmaf(x.x * w.x, y.x, bm.x), 0.f);
    r.y = fmaxf(fmaf(x.y * w.y, y.y, bm.y), 0.f);
    r.z = fmaxf(fmaf(x.z * w.z, y.z, bm.z), 0.f);
    r.w = fmaxf(fmaf(x.w * w.w, y.w, bm.w), 0.f);
    return r;
}

struct PathSmem {
    float sW[3 * EMB];
    float sB[3 * EMB];
    float sAcc[8][256];
    float sCnt[8];
};

// One block per (batch row b, group). 8 warps; warp w handles paths
// p = w, w+8, w+16, w+24 with 1-path lookahead prefetch of embedding rows.
template<int L>
__device__ __forceinline__ void path_body(
    PathSmem& sm,
    const int*   __restrict__ ents,
    const int*   __restrict__ mids,
    const float* __restrict__ counts,
    const float* __restrict__ E,
    const float* __restrict__ Wm,
    const float* __restrict__ Bm,
    int gofs)
{
    const int b    = blockIdx.x;
    const int tid  = threadIdx.x;
    const int wid  = tid >> 5;
    const int lane = tid & 31;

    for (int i = tid; i < 3 * EMB; i += 256) { sm.sW[i] = Wm[i]; sm.sB[i] = Bm[i]; }
    __syncthreads();

    int   e[4][L + 1];
    int   m[4][L];
    float cnt[4];
    #pragma unroll
    for (int pp = 0; pp < 4; pp++) {
        const long base = (long)b * PSZ + (wid + pp * 8);
        const int* ep = ents + base * (L + 1);
        const int* mp = mids + base * L;
        #pragma unroll
        for (int i = 0; i <= L; i++) e[pp][i] = ep[i];
        #pragma unroll
        for (int i = 0; i < L; i++)  m[pp][i] = mp[i];
        cnt[pp] = counts[base];
    }

    float4 a1 = make_float4(0.f, 0.f, 0.f, 0.f);
    float4 a2 = make_float4(0.f, 0.f, 0.f, 0.f);
    float  cs = 0.f;

    float4 buf[2][L + 1];
    #pragma unroll
    for (int i = 0; i <= L; i++)
        buf[0][i] = *(const float4*)(E + (long)e[0][i] * EMB + lane * 4);

    #pragma unroll
    for (int pp = 0; pp < 4; pp++) {
        if (pp < 3) {
            #pragma unroll
            for (int i = 0; i <= L; i++)
                buf[(pp + 1) & 1][i] =
                    *(const float4*)(E + (long)e[pp + 1][i] * EMB + lane * 4);
        }
        float4 (&rows)[L + 1] = buf[pp & 1];

        // forward
        float4 x = rows[0];
        #pragma unroll
        for (int i = 0; i < L; i++) {
            float4 w  = *(const float4*)(sm.sW + m[pp][i] * EMB + lane * 4);
            float4 bb = *(const float4*)(sm.sB + m[pp][i] * EMB + lane * 4);
            x = relu_step(x, w, rows[i + 1], bb);
        }
        const float4 o1 = x;

        // backward: start x and (stale) y are both E[ents[L]]
        const float4 yl = rows[L];
        x = yl;
        #pragma unroll
        for (int i = L - 1; i >= 0; i--) {
            float4 w  = *(const float4*)(sm.sW + m[pp][i] * EMB + lane * 4);
            float4 bb = *(const float4*)(sm.sB + m[pp][i] * EMB + lane * 4);
            x = relu_step(x, w, yl, bb);
        }

        const float c0 = cnt[pp];
        a1.x += c0 * o1.x; a1.y += c0 * o1.y; a1.z += c0 * o1.z; a1.w += c0 * o1.w;
        a2.x += c0 * x.x;  a2.y += c0 * x.y;  a2.z += c0 * x.z;  a2.w += c0 * x.w;
        cs   += c0;
    }

    ((float4*)sm.sAcc[wid])[lane]         = a1;
    ((float4*)(sm.sAcc[wid] + 128))[lane] = a2;
    if (lane == 0) sm.sCnt[wid] = cs;
    __syncthreads();

    float s = 0.f, csum = 0.f;
    #pragma unroll
    for (int w = 0; w < 8; w++) { s += sm.sAcc[w][tid]; csum += sm.sCnt[w]; }
    g_H[(long)b * HDIM + gofs + tid] = s / csum;
}

__global__ __launch_bounds__(256) void paths_kernel(
    const int* __restrict__ ent1, const int* __restrict__ mid1, const float* __restrict__ c1,
    const int* __restrict__ ent2, const int* __restrict__ mid2, const float* __restrict__ c2,
    const int* __restrict__ ent3, const int* __restrict__ mid3, const float* __restrict__ c3,
    const float* __restrict__ E, const float* __restrict__ Wm, const float* __restrict__ Bm)
{
    __shared__ PathSmem sm;
    const int g = blockIdx.y;
    if (g == 0)      path_body<1>(sm, ent1, mid1, c1, E, Wm, Bm, 0);
    else if (g == 1) path_body<2>(sm, ent2, mid2, c2, E, Wm, Bm, 256);
    else             path_body<3>(sm, ent3, mid3, c3, E, Wm, Bm, 512);
}

// ────────────────────────────────────────────────────────────────────────
// MLP head: 16 rows/block, 512 threads, 256 blocks.
// Phase A uses explicit double-buffered W1 register chunks (wA/wB, 16 k
// each): 16 LDGs issued as a burst one half-chunk ahead of consumption.
// ────────────────────────────────────────────────────────────────────────
#define WCONSUME(WBUF, KC)                                                  \
    do {                                                                    \
        _Pragma("unroll")                                                   \
        for (int g = 0; g < 4; g++) {                                       \
            const int kb = (KC) + g * 4;                                    \
            _Pragma("unroll")                                               \
            for (int r = 0; r < 4; r++) {                                   \
                const float4 h = *(const float4*)(sH + (rbase + r) * HDIM + kb); \
                acc[r] = fmaf(h.x, WBUF[g * 4 + 0], acc[r]);                \
                acc[r] = fmaf(h.y, WBUF[g * 4 + 1], acc[r]);                \
                acc[r] = fmaf(h.z, WBUF[g * 4 + 2], acc[r]);                \
                acc[r] = fmaf(h.w, WBUF[g * 4 + 3], acc[r]);                \
            }                                                               \
        }                                                                   \
    } while (0)

__global__ __launch_bounds__(512, 2) void mlp_kernel(
    const float* __restrict__ W1, const float* __restrict__ b1,
    const float* __restrict__ W2, const float* __restrict__ b2,
    const float* __restrict__ W3, const float* __restrict__ b3,
    float* __restrict__ out)
{
    __shared__ float smem[MROWS * HDIM];        // 48 KB
    float* const sH = smem;

    const int b0  = blockIdx.x * MROWS;
    const int tid = threadIdx.x;

    // Load full H tile (3072 float4, 6 per thread)
    {
        const float4* src = (const float4*)(g_H + (long)b0 * HDIM);
        float4*       dst = (float4*)sH;
        #pragma unroll
        for (int i = 0; i < (MROWS * HDIM / 4) / 512; i++)
            dst[tid + i * 512] = src[tid + i * 512];
    }
    __syncthreads();

    // ── Phase A: h1 = relu(H @ W1 + b1), [16,128] ────────────────────────
    const int c     = tid & 127;
    const int rbase = (tid >> 7) * 4;     // 0,4,8,12
    float acc[4];
    {
        const float bias1 = b1[c];
        #pragma unroll
        for (int r = 0; r < 4; r++) acc[r] = bias1;
    }

    const float* const wp = W1 + c;
    float wA[16], wB[16];
    #pragma unroll
    for (int j = 0; j < 16; j++) wA[j] = __ldg(wp + j * 128);
    #pragma unroll
    for (int j = 0; j < 16; j++) wB[j] = __ldg(wp + (16 + j) * 128);

    // Main loop: kc = 0,32,...,704. Each iter consumes [kc,kc+32) and
    // prefetches [kc+32,kc+64) (max load k = 767 — in bounds).
    #pragma unroll 1
    for (int kc = 0; kc <= HDIM - 64; kc += 32) {
        WCONSUME(wA, kc);
        #pragma unroll
        for (int j = 0; j < 16; j++) wA[j] = __ldg(wp + (kc + 32 + j) * 128);
        WCONSUME(wB, kc + 16);
        #pragma unroll
        for (int j = 0; j < 16; j++) wB[j] = __ldg(wp + (kc + 48 + j) * 128);
    }
    // Epilogue: k = [736,768) already resident in wA/wB.
    WCONSUME(wA, HDIM - 32);
    WCONSUME(wB, HDIM - 16);
    __syncthreads();          // everyone done reading sH

    float* const sh1 = smem;                 // [16][128]
    float* const sh2 = smem + MROWS * 128;   // [16][32]
    #pragma unroll
    for (int r = 0; r < 4; r++)
        sh1[(rbase + r) * 128 + c] = fmaxf(acc[r], 0.f);
    __syncthreads();

    // ── Phase B: h2 = relu(h1 @ W2 + b2), [16,32] — 512 thr = 16r × 32c ──
    {
        const int c2 = tid & 31;
        const int r  = tid >> 5;   // 0..15
        float a = b2[c2];
        #pragma unroll 8
        for (int k = 0; k < 128; k += 4) {
            const float4 h = *(const float4*)(sh1 + r * 128 + k);
            a = fmaf(h.x, __ldg(W2 + (k    ) * 32 + c2), a);
            a = fmaf(h.y, __ldg(W2 + (k + 1) * 32 + c2), a);
            a = fmaf(h.z, __ldg(W2 + (k + 2) * 32 + c2), a);
            a = fmaf(h.w, __ldg(W2 + (k + 3) * 32 + c2), a);
        }
        sh2[r * 32 + c2] = fmaxf(a, 0.f);
    }
    __syncthreads();

    // ── Phase C: out = h2 @ W3 + b3, [16,1] ─────────────────────────────
    if (tid < MROWS) {
        float a = b3[0];
        #pragma unroll
        for (int k = 0; k < 32; k++) a = fmaf(sh2[tid * 32 + k], W3[k], a);
        out[b0 + tid] = a;
    }
}

extern "C" void kernel_launch(void* const* d_in, const int* in_sizes, int n_in,
                              void* d_out, int out_size)
{
    const bool dictOrder = (in_sizes[2] == BSZ * PSZ);

    const int *ent1, *mid1, *ent2, *mid2, *ent3, *mid3;
    const float *c1, *c2, *c3;
    if (dictOrder) {
        ent1 = (const int*)d_in[0]; mid1 = (const int*)d_in[1]; c1 = (const float*)d_in[2];
        ent2 = (const int*)d_in[3]; mid2 = (const int*)d_in[4]; c2 = (const float*)d_in[5];
        ent3 = (const int*)d_in[6]; mid3 = (const int*)d_in[7]; c3 = (const float*)d_in[8];
    } else {
        ent1 = (const int*)d_in[0]; mid1 = (const int*)d_in[1];
        ent2 = (const int*)d_in[2]; mid2 = (const int*)d_in[3];
        ent3 = (const int*)d_in[4]; mid3 = (const int*)d_in[5];
        c1 = (const float*)d_in[6]; c2 = (const float*)d_in[7]; c3 = (const float*)d_in[8];
    }
    const float* E  = (const float*)d_in[9];
    const float* Wm = (const float*)d_in[10];
    const float* Bm = (const float*)d_in[11];
    const float* W1 = (const float*)d_in[12];
    const float* b1 = (const float*)d_in[13];
    const float* W2 = (const float*)d_in[14];
    const float* b2 = (const float*)d_in[15];
    const float* W3 = (const float*)d_in[16];
    const float* b3 = (const float*)d_in[17];

    dim3 pgrid(BSZ, 3);
    paths_kernel<<<pgrid, 256>>>(ent1, mid1, c1, ent2, mid2, c2, ent3, mid3, c3,
                                 E, Wm, Bm);
    mlp_kernel<<<BSZ / MROWS, 512>>>(W1, b1, W2, b2, W3, b3, (float*)d_out);
}